// round 9
// baseline (speedup 1.0000x reference)
#include <cuda_runtime.h>
#include <cuda_fp16.h>
#include <cstdint>

#define MAXN 50048
#define MAXE 860000

// ---------------- scratch ----------------
__device__ __half g_h[MAXN * 128];     // fp16 messages (per layer)
__device__ float  g_x2[MAXN * 128];    // relu(layer1 out), fp32 (GEMM2 input)
__device__ float  g_as[MAXN];
__device__ float  g_ad[MAXN];
__device__ int    g_deg[MAXN];
__device__ int    g_cursor[MAXN];
__device__ int    g_rowptr[MAXN + 1];
__device__ int    g_esorted[MAXE];
__device__ int    g_blocksum[64];

// ---------------- f32x2 helpers ----------------
__device__ __forceinline__ unsigned long long pack_dup(float a) {
    unsigned long long r;
    asm("mov.b64 %0, {%1, %1};" : "=l"(r) : "f"(a));
    return r;
}
__device__ __forceinline__ void unpack2(unsigned long long p, float& lo, float& hi) {
    asm("mov.b64 {%0, %1}, %2;" : "=f"(lo), "=f"(hi) : "l"(p));
}
__device__ __forceinline__ unsigned long long fma2(unsigned long long a,
                                                   unsigned long long b,
                                                   unsigned long long c) {
    unsigned long long d;
    asm("fma.rn.f32x2 %0, %1, %2, %3;" : "=l"(d) : "l"(a), "l"(b), "l"(c));
    return d;
}

// ---------------- fused GEMM (+alpha epilogue, fp16 C) [+ optional hist tail] ----------------
template <int BN, bool WITH_HIST>
__global__ void gemm_alpha_kernel(const float* __restrict__ A, const float* __restrict__ B,
                                  __half* __restrict__ Ch,
                                  const float* __restrict__ avs, const float* __restrict__ avd,
                                  int M, int K,
                                  const int* __restrict__ dst, int E, int ET, int gemmBlocks) {
    if (WITH_HIST && blockIdx.x >= gemmBlocks) {
        int i = (blockIdx.x - gemmBlocks) * blockDim.x + threadIdx.x;
        if (i < ET) {
            int d = (i < E) ? __ldg(&dst[i]) : (i - E);
            atomicAdd(&g_deg[d], 1);
        }
        return;
    }
    constexpr int TN = BN / 16;
    constexpr int TP = TN / 2;
    __align__(16) __shared__ float As[8][128];
    __align__(16) __shared__ float Bs[8][BN];
    const int tid = threadIdx.x;
    const int tx = tid & 15;
    const int ty = tid >> 4;
    const int bm = blockIdx.x * 128;

    unsigned long long acc2[8][TP];
#pragma unroll
    for (int i = 0; i < 8; i++)
#pragma unroll
        for (int j = 0; j < TP; j++) acc2[i][j] = 0ull;

    for (int k0 = 0; k0 < K; k0 += 8) {
        {
            int ar = tid >> 1;
            int ak = (tid & 1) * 4;
            int gr = bm + ar;
            float4 v = make_float4(0.f, 0.f, 0.f, 0.f);
            if (gr < M) v = *reinterpret_cast<const float4*>(&A[(size_t)gr * K + k0 + ak]);
            As[ak + 0][ar] = v.x;
            As[ak + 1][ar] = v.y;
            As[ak + 2][ar] = v.z;
            As[ak + 3][ar] = v.w;
        }
        if (BN == 128) {
            int br = tid >> 5;
            int bc = (tid & 31) * 4;
            *reinterpret_cast<float4*>(&Bs[br][bc]) =
                *reinterpret_cast<const float4*>(&B[(size_t)(k0 + br) * BN + bc]);
        } else {
            if (tid < 128) {
                int br = tid >> 4;
                int bc = (tid & 15) * 4;
                *reinterpret_cast<float4*>(&Bs[br][bc]) =
                    *reinterpret_cast<const float4*>(&B[(size_t)(k0 + br) * BN + bc]);
            }
        }
        __syncthreads();
#pragma unroll
        for (int kk = 0; kk < 8; kk++) {
            float a[8];
            float4 a0 = *reinterpret_cast<const float4*>(&As[kk][ty * 8]);
            float4 a1 = *reinterpret_cast<const float4*>(&As[kk][ty * 8 + 4]);
            a[0] = a0.x; a[1] = a0.y; a[2] = a0.z; a[3] = a0.w;
            a[4] = a1.x; a[5] = a1.y; a[6] = a1.z; a[7] = a1.w;
            unsigned long long b2[TP];
#pragma unroll
            for (int j = 0; j < TP; j++)
                b2[j] = *reinterpret_cast<const unsigned long long*>(&Bs[kk][tx * TN + 2 * j]);
#pragma unroll
            for (int i = 0; i < 8; i++) {
                unsigned long long ad = pack_dup(a[i]);
#pragma unroll
                for (int j = 0; j < TP; j++) acc2[i][j] = fma2(ad, b2[j], acc2[i][j]);
            }
        }
        __syncthreads();
    }

    float asv[TN], adv[TN];
#pragma unroll
    for (int j = 0; j < TN; j += 4) {
        float4 v = *reinterpret_cast<const float4*>(&avs[tx * TN + j]);
        asv[j] = v.x; asv[j + 1] = v.y; asv[j + 2] = v.z; asv[j + 3] = v.w;
        float4 w = *reinterpret_cast<const float4*>(&avd[tx * TN + j]);
        adv[j] = w.x; adv[j + 1] = w.y; adv[j + 2] = w.z; adv[j + 3] = w.w;
    }

#pragma unroll
    for (int i = 0; i < 8; i++) {
        int gr = bm + ty * 8 + i;
        float c[TN];
#pragma unroll
        for (int j = 0; j < TP; j++) unpack2(acc2[i][j], c[2 * j], c[2 * j + 1]);
        if (gr < M) {
            // fp16 store: TN halves (16B for TN=8, 8B for TN=4)
            __half2 hb[TP];
#pragma unroll
            for (int j = 0; j < TP; j++)
                hb[j] = __floats2half2_rn(c[2 * j], c[2 * j + 1]);
            if (TN == 8) {
                uint4 st;
                st.x = *reinterpret_cast<unsigned*>(&hb[0]);
                st.y = *reinterpret_cast<unsigned*>(&hb[1]);
                st.z = *reinterpret_cast<unsigned*>(&hb[2]);
                st.w = *reinterpret_cast<unsigned*>(&hb[3]);
                *reinterpret_cast<uint4*>(&Ch[(size_t)gr * BN + tx * TN]) = st;
            } else {
                uint2 st;
                st.x = *reinterpret_cast<unsigned*>(&hb[0]);
                st.y = *reinterpret_cast<unsigned*>(&hb[1]);
                *reinterpret_cast<uint2*>(&Ch[(size_t)gr * BN + tx * TN]) = st;
            }
        }
        float s = 0.f, d = 0.f;
#pragma unroll
        for (int j = 0; j < TN; j++) {
            s = fmaf(c[j], asv[j], s);
            d = fmaf(c[j], adv[j], d);
        }
#pragma unroll
        for (int o = 8; o > 0; o >>= 1) {
            s += __shfl_xor_sync(0xffffffffu, s, o);
            d += __shfl_xor_sync(0xffffffffu, d, o);
        }
        if (tx == 0 && gr < M) {
            g_as[gr] = s;
            g_ad[gr] = d;
        }
    }
}

// ---------------- scans ----------------
__global__ void scan_partial_kernel(int N) {
    __shared__ int wsum[32];
    int t = threadIdx.x;
    int i = blockIdx.x * 1024 + t;
    int v = (i < N) ? g_deg[i] : 0;
#pragma unroll
    for (int o = 16; o > 0; o >>= 1) v += __shfl_xor_sync(0xffffffffu, v, o);
    if ((t & 31) == 0) wsum[t >> 5] = v;
    __syncthreads();
    if (t < 32) {
        int x = wsum[t];
#pragma unroll
        for (int o = 16; o > 0; o >>= 1) x += __shfl_xor_sync(0xffffffffu, x, o);
        if (t == 0) g_blocksum[blockIdx.x] = x;
    }
}

__global__ void scan_final_kernel(int N, int nb) {
    __shared__ int wsum[32];
    __shared__ int bsm[64];
    __shared__ int base_sh;
    int t = threadIdx.x;
    int lane = t & 31;
    int wid = t >> 5;
    int i = blockIdx.x * 1024 + t;
    int v = (i < N) ? g_deg[i] : 0;
    int x = v;
#pragma unroll
    for (int o = 1; o < 32; o <<= 1) {
        int y = __shfl_up_sync(0xffffffffu, x, o);
        if (lane >= o) x += y;
    }
    if (lane == 31) wsum[wid] = x;
    if (t < nb) bsm[t] = g_blocksum[t];
    __syncthreads();
    if (t < 32) {
        int w = wsum[t];
#pragma unroll
        for (int o = 1; o < 32; o <<= 1) {
            int y = __shfl_up_sync(0xffffffffu, w, o);
            if (t >= o) w += y;
        }
        wsum[t] = w;
    }
    if (t == 0) {
        int s = 0;
        for (int j = 0; j < blockIdx.x; j++) s += bsm[j];
        base_sh = s;
        if (blockIdx.x == 0) {
            int tot = 0;
            for (int j = 0; j < nb; j++) tot += bsm[j];
            g_rowptr[N] = tot;
        }
    }
    __syncthreads();
    int incl = x + ((wid > 0) ? wsum[wid - 1] : 0);
    int excl = base_sh + incl - v;
    if (i < N) {
        g_rowptr[i] = excl;
        g_cursor[i] = excl;
    }
}

// ---------------- fill (4 edges per thread for atomic MLP) ----------------
__global__ void fill_kernel(const int* __restrict__ src, const int* __restrict__ dst,
                            int E, int ET) {
    int t = blockIdx.x * blockDim.x + threadIdx.x;
    int nv = E >> 2;
    if (t < nv) {
        int4 s4 = reinterpret_cast<const int4*>(src)[t];
        int4 d4 = reinterpret_cast<const int4*>(dst)[t];
        int p0 = atomicAdd(&g_cursor[d4.x], 1);
        int p1 = atomicAdd(&g_cursor[d4.y], 1);
        int p2 = atomicAdd(&g_cursor[d4.z], 1);
        int p3 = atomicAdd(&g_cursor[d4.w], 1);
        g_esorted[p0] = s4.x;
        g_esorted[p1] = s4.y;
        g_esorted[p2] = s4.z;
        g_esorted[p3] = s4.w;
    } else {
        int i = (E & ~3) + (t - nv);
        if (i < ET) {
            int s, d;
            if (i < E) { s = __ldg(&src[i]); d = __ldg(&dst[i]); }
            else       { s = d = i - E; }
            int pos = atomicAdd(&g_cursor[d], 1);
            g_esorted[pos] = s;
        }
    }
}

// ---------------- gather: per-dst lane-group, fp16 messages, fp32 accumulate ----------------
template <int F4, bool RELU>
__global__ void gather_kernel(const __half* __restrict__ h,
                              const float* __restrict__ bias,
                              float* __restrict__ out, int N) {
    constexpr int NPW = 32 / F4;
    int warp = (blockIdx.x * blockDim.x + threadIdx.x) >> 5;
    int lane = threadIdx.x & 31;
    int sub = lane / F4;
    int li = lane % F4;
    int d = warp * NPW + sub;
    const unsigned gmask = ((F4 == 32) ? 0xffffffffu : ((1u << F4) - 1u) << (sub * F4));

    int start = 0, end = 0;
    float ad = 0.0f;
    if (d < N) {
        start = g_rowptr[d];
        end = g_rowptr[d + 1];
        ad = g_ad[d];
    }

    float4 acc = make_float4(0.f, 0.f, 0.f, 0.f);
    float den = 0.0f;
    const uint2* h4 = reinterpret_cast<const uint2*>(h);  // 4 halves per element

    for (int e0 = start; e0 < end; e0 += F4) {
        int mye = e0 + li;
        float w = 0.0f;
        int s = 0;
        if (mye < end) {
            s = g_esorted[mye];
            float sc = g_as[s] + ad;
            sc = (sc >= 0.0f) ? sc : 0.2f * sc;
            w = __expf(sc);
        }
        den += w;
        int cnt = min(F4, end - e0);
        for (int j = 0; j < cnt; j++) {
            float wj = __shfl_sync(gmask, w, sub * F4 + j);
            int sj = __shfl_sync(gmask, s, sub * F4 + j);
            uint2 hv = h4[(size_t)sj * F4 + li];
            float2 f0 = __half22float2(*reinterpret_cast<__half2*>(&hv.x));
            float2 f1 = __half22float2(*reinterpret_cast<__half2*>(&hv.y));
            acc.x = fmaf(wj, f0.x, acc.x);
            acc.y = fmaf(wj, f0.y, acc.y);
            acc.z = fmaf(wj, f1.x, acc.z);
            acc.w = fmaf(wj, f1.y, acc.w);
        }
    }
#pragma unroll
    for (int o = F4 / 2; o > 0; o >>= 1) den += __shfl_xor_sync(gmask, den, o);

    if (d < N) {
        float r = __frcp_rn(den);
        float4 b4 = reinterpret_cast<const float4*>(bias)[li];
        float4 v;
        v.x = fmaf(acc.x, r, b4.x);
        v.y = fmaf(acc.y, r, b4.y);
        v.z = fmaf(acc.z, r, b4.z);
        v.w = fmaf(acc.w, r, b4.w);
        if (RELU) {
            v.x = fmaxf(v.x, 0.f); v.y = fmaxf(v.y, 0.f);
            v.z = fmaxf(v.z, 0.f); v.w = fmaxf(v.w, 0.f);
        }
        reinterpret_cast<float4*>(out)[(size_t)d * F4 + li] = v;
    }
}

// ---------------- launch ----------------
extern "C" void kernel_launch(void* const* d_in, const int* in_sizes, int n_in,
                              void* d_out, int out_size) {
    const float* X     = (const float*)d_in[0];
    const int*   EI    = (const int*)d_in[1];
    const float* W1    = (const float*)d_in[2];
    const float* asrc1 = (const float*)d_in[3];
    const float* adst1 = (const float*)d_in[4];
    const float* b1    = (const float*)d_in[5];
    const float* W2    = (const float*)d_in[6];
    const float* asrc2 = (const float*)d_in[7];
    const float* adst2 = (const float*)d_in[8];
    const float* b2    = (const float*)d_in[9];
    float* out = (float*)d_out;

    const int F_IN = 128;
    const int N = in_sizes[0] / F_IN;
    const int E = in_sizes[1] / 2;
    const int ET = E + N;
    const int* src = EI;
    const int* dst = EI + E;

    __half* p_h;
    float* p_x2;
    int* p_deg;
    cudaGetSymbolAddress((void**)&p_h, g_h);
    cudaGetSymbolAddress((void**)&p_x2, g_x2);
    cudaGetSymbolAddress((void**)&p_deg, g_deg);

    const int BT = 256;
    const int nb = (N + 1023) / 1024;
    const int histB = (ET + BT - 1) / BT;
    const int gB1 = (N + 127) / 128;

    cudaMemsetAsync(p_deg, 0, (size_t)N * sizeof(int));

    // GEMM1 (+alpha1) || hist
    gemm_alpha_kernel<128, true><<<gB1 + histB, BT>>>(X, W1, p_h, asrc1, adst1,
                                                      N, F_IN, dst, E, ET, gB1);
    // CSR scan + fill
    scan_partial_kernel<<<nb, 1024>>>(N);
    scan_final_kernel<<<nb, 1024>>>(N, nb);
    {
        int fillT = (E >> 2) + (ET - (E & ~3));
        fill_kernel<<<(fillT + BT - 1) / BT, BT>>>(src, dst, E, ET);
    }

    // gather layer 1 -> x2 (relu)
    gather_kernel<32, true><<<(N * 32 + BT - 1) / BT, BT>>>(p_h, b1, p_x2, N);

    // GEMM2 (+alpha2)
    gemm_alpha_kernel<64, false><<<gB1, BT>>>(p_x2, W2, p_h, asrc2, adst2,
                                              N, 128, nullptr, 0, 0, gB1);

    // gather layer 2 -> out
    {
        long warps = (N + 1) / 2;
        gather_kernel<16, false><<<(unsigned)((warps * 32 + BT - 1) / BT), BT>>>(p_h, b2, out, N);
    }
}

// round 10
// speedup vs baseline: 1.0905x; 1.0905x over previous
#include <cuda_runtime.h>
#include <cstdint>

#define MAXN 50048
#define MAXE 860000

// ---------------- scratch ----------------
__device__ float g_h[MAXN * 128];
__device__ float g_x2[MAXN * 128];
__device__ float g_as[MAXN];
__device__ float g_ad[MAXN];
__device__ int   g_deg[MAXN];
__device__ int   g_rank[MAXE];
__device__ int   g_rowptr[MAXN + 1];
__device__ int   g_esorted[MAXE];
__device__ int   g_blocksum[64];

// ---------------- f32x2 helpers ----------------
__device__ __forceinline__ unsigned long long pack_dup(float a) {
    unsigned long long r;
    asm("mov.b64 %0, {%1, %1};" : "=l"(r) : "f"(a));
    return r;
}
__device__ __forceinline__ void unpack2(unsigned long long p, float& lo, float& hi) {
    asm("mov.b64 {%0, %1}, %2;" : "=f"(lo), "=f"(hi) : "l"(p));
}
__device__ __forceinline__ unsigned long long fma2(unsigned long long a,
                                                   unsigned long long b,
                                                   unsigned long long c) {
    unsigned long long d;
    asm("fma.rn.f32x2 %0, %1, %2, %3;" : "=l"(d) : "l"(a), "l"(b), "l"(c));
    return d;
}

// ---------------- fused GEMM (+alpha epilogue), fp32 C ----------------
template <int BN>
__global__ void gemm_alpha_kernel(const float* __restrict__ A, const float* __restrict__ B,
                                  float* __restrict__ C,
                                  const float* __restrict__ avs, const float* __restrict__ avd,
                                  int M, int K) {
    constexpr int TN = BN / 16;
    constexpr int TP = TN / 2;
    __align__(16) __shared__ float As[8][128];
    __align__(16) __shared__ float Bs[8][BN];
    const int tid = threadIdx.x;
    const int tx = tid & 15;
    const int ty = tid >> 4;
    const int bm = blockIdx.x * 128;

    unsigned long long acc2[8][TP];
#pragma unroll
    for (int i = 0; i < 8; i++)
#pragma unroll
        for (int j = 0; j < TP; j++) acc2[i][j] = 0ull;

    for (int k0 = 0; k0 < K; k0 += 8) {
        {
            int ar = tid >> 1;
            int ak = (tid & 1) * 4;
            int gr = bm + ar;
            float4 v = make_float4(0.f, 0.f, 0.f, 0.f);
            if (gr < M) v = *reinterpret_cast<const float4*>(&A[(size_t)gr * K + k0 + ak]);
            As[ak + 0][ar] = v.x;
            As[ak + 1][ar] = v.y;
            As[ak + 2][ar] = v.z;
            As[ak + 3][ar] = v.w;
        }
        if (BN == 128) {
            int br = tid >> 5;
            int bc = (tid & 31) * 4;
            *reinterpret_cast<float4*>(&Bs[br][bc]) =
                *reinterpret_cast<const float4*>(&B[(size_t)(k0 + br) * BN + bc]);
        } else {
            if (tid < 128) {
                int br = tid >> 4;
                int bc = (tid & 15) * 4;
                *reinterpret_cast<float4*>(&Bs[br][bc]) =
                    *reinterpret_cast<const float4*>(&B[(size_t)(k0 + br) * BN + bc]);
            }
        }
        __syncthreads();
#pragma unroll
        for (int kk = 0; kk < 8; kk++) {
            float a[8];
            float4 a0 = *reinterpret_cast<const float4*>(&As[kk][ty * 8]);
            float4 a1 = *reinterpret_cast<const float4*>(&As[kk][ty * 8 + 4]);
            a[0] = a0.x; a[1] = a0.y; a[2] = a0.z; a[3] = a0.w;
            a[4] = a1.x; a[5] = a1.y; a[6] = a1.z; a[7] = a1.w;
            unsigned long long b2[TP];
#pragma unroll
            for (int j = 0; j < TP; j++)
                b2[j] = *reinterpret_cast<const unsigned long long*>(&Bs[kk][tx * TN + 2 * j]);
#pragma unroll
            for (int i = 0; i < 8; i++) {
                unsigned long long ad = pack_dup(a[i]);
#pragma unroll
                for (int j = 0; j < TP; j++) acc2[i][j] = fma2(ad, b2[j], acc2[i][j]);
            }
        }
        __syncthreads();
    }

    float asv[TN], adv[TN];
#pragma unroll
    for (int j = 0; j < TN; j += 4) {
        float4 v = *reinterpret_cast<const float4*>(&avs[tx * TN + j]);
        asv[j] = v.x; asv[j + 1] = v.y; asv[j + 2] = v.z; asv[j + 3] = v.w;
        float4 w = *reinterpret_cast<const float4*>(&avd[tx * TN + j]);
        adv[j] = w.x; adv[j + 1] = w.y; adv[j + 2] = w.z; adv[j + 3] = w.w;
    }

#pragma unroll
    for (int i = 0; i < 8; i++) {
        int gr = bm + ty * 8 + i;
        float c[TN];
#pragma unroll
        for (int j = 0; j < TP; j++) unpack2(acc2[i][j], c[2 * j], c[2 * j + 1]);
        if (gr < M) {
#pragma unroll
            for (int j = 0; j < TN; j += 4) {
                float4 v = make_float4(c[j], c[j + 1], c[j + 2], c[j + 3]);
                *reinterpret_cast<float4*>(&C[(size_t)gr * BN + tx * TN + j]) = v;
            }
        }
        float s = 0.f, d = 0.f;
#pragma unroll
        for (int j = 0; j < TN; j++) {
            s = fmaf(c[j], asv[j], s);
            d = fmaf(c[j], adv[j], d);
        }
#pragma unroll
        for (int o = 8; o > 0; o >>= 1) {
            s += __shfl_xor_sync(0xffffffffu, s, o);
            d += __shfl_xor_sync(0xffffffffu, d, o);
        }
        if (tx == 0 && gr < M) {
            g_as[gr] = s;
            g_ad[gr] = d;
        }
    }
}

// ---------------- hist + per-edge rank ----------------
__global__ void hist_kernel(const int* __restrict__ dst, int E, int ET) {
    int i = blockIdx.x * blockDim.x + threadIdx.x;
    if (i >= ET) return;
    int d = (i < E) ? __ldg(&dst[i]) : (i - E);
    g_rank[i] = atomicAdd(&g_deg[d], 1);
}

// ---------------- scans ----------------
__global__ void scan_partial_kernel(int N) {
    __shared__ int wsum[32];
    int t = threadIdx.x;
    int i = blockIdx.x * 1024 + t;
    int v = (i < N) ? g_deg[i] : 0;
#pragma unroll
    for (int o = 16; o > 0; o >>= 1) v += __shfl_xor_sync(0xffffffffu, v, o);
    if ((t & 31) == 0) wsum[t >> 5] = v;
    __syncthreads();
    if (t < 32) {
        int x = wsum[t];
#pragma unroll
        for (int o = 16; o > 0; o >>= 1) x += __shfl_xor_sync(0xffffffffu, x, o);
        if (t == 0) g_blocksum[blockIdx.x] = x;
    }
}

__global__ void scan_final_kernel(int N, int nb) {
    __shared__ int wsum[32];
    __shared__ int bsm[64];
    __shared__ int base_sh;
    int t = threadIdx.x;
    int lane = t & 31;
    int wid = t >> 5;
    int i = blockIdx.x * 1024 + t;
    int v = (i < N) ? g_deg[i] : 0;
    int x = v;
#pragma unroll
    for (int o = 1; o < 32; o <<= 1) {
        int y = __shfl_up_sync(0xffffffffu, x, o);
        if (lane >= o) x += y;
    }
    if (lane == 31) wsum[wid] = x;
    if (t < nb) bsm[t] = g_blocksum[t];
    __syncthreads();
    if (t < 32) {
        int w = wsum[t];
#pragma unroll
        for (int o = 1; o < 32; o <<= 1) {
            int y = __shfl_up_sync(0xffffffffu, w, o);
            if (t >= o) w += y;
        }
        wsum[t] = w;
    }
    if (t == 0) {
        int s = 0;
        for (int j = 0; j < blockIdx.x; j++) s += bsm[j];
        base_sh = s;
        if (blockIdx.x == 0) {
            int tot = 0;
            for (int j = 0; j < nb; j++) tot += bsm[j];
            g_rowptr[N] = tot;
        }
    }
    __syncthreads();
    int incl = x + ((wid > 0) ? wsum[wid - 1] : 0);
    int excl = base_sh + incl - v;
    if (i < N) g_rowptr[i] = excl;
}

// ---------------- fill: no atomics (rank precomputed in hist) ----------------
__global__ void fill_kernel(const int* __restrict__ src, const int* __restrict__ dst,
                            int E, int ET) {
    int i = blockIdx.x * blockDim.x + threadIdx.x;
    if (i >= ET) return;
    int s, d;
    if (i < E) { s = __ldg(&src[i]); d = __ldg(&dst[i]); }
    else       { s = d = i - E; }
    g_esorted[g_rowptr[d] + g_rank[i]] = s;
}

// ---------------- gather: per-dst lane-group, fp32, fused softmax+agg+bias(+relu) ----------------
template <int F4, bool RELU>
__global__ void gather_kernel(const float* __restrict__ h,
                              const float* __restrict__ bias,
                              float* __restrict__ out, int N) {
    constexpr int NPW = 32 / F4;
    int warp = (blockIdx.x * blockDim.x + threadIdx.x) >> 5;
    int lane = threadIdx.x & 31;
    int sub = lane / F4;
    int li = lane % F4;
    int d = warp * NPW + sub;
    const unsigned gmask = ((F4 == 32) ? 0xffffffffu : ((1u << F4) - 1u) << (sub * F4));

    int start = 0, end = 0;
    float ad = 0.0f;
    if (d < N) {
        start = g_rowptr[d];
        end = g_rowptr[d + 1];
        ad = g_ad[d];
    }

    float4 acc = make_float4(0.f, 0.f, 0.f, 0.f);
    float den = 0.0f;
    const float4* h4 = reinterpret_cast<const float4*>(h);

    for (int e0 = start; e0 < end; e0 += F4) {
        int mye = e0 + li;
        float w = 0.0f;
        int s = 0;
        if (mye < end) {
            s = g_esorted[mye];
            float sc = g_as[s] + ad;
            sc = (sc >= 0.0f) ? sc : 0.2f * sc;
            w = __expf(sc);
        }
        den += w;
        int cnt = min(F4, end - e0);
        for (int j = 0; j < cnt; j++) {
            float wj = __shfl_sync(gmask, w, sub * F4 + j);
            int sj = __shfl_sync(gmask, s, sub * F4 + j);
            float4 hv = h4[(size_t)sj * F4 + li];
            acc.x = fmaf(wj, hv.x, acc.x);
            acc.y = fmaf(wj, hv.y, acc.y);
            acc.z = fmaf(wj, hv.z, acc.z);
            acc.w = fmaf(wj, hv.w, acc.w);
        }
    }
#pragma unroll
    for (int o = F4 / 2; o > 0; o >>= 1) den += __shfl_xor_sync(gmask, den, o);

    if (d < N) {
        float r = __frcp_rn(den);
        float4 b4 = reinterpret_cast<const float4*>(bias)[li];
        float4 v;
        v.x = fmaf(acc.x, r, b4.x);
        v.y = fmaf(acc.y, r, b4.y);
        v.z = fmaf(acc.z, r, b4.z);
        v.w = fmaf(acc.w, r, b4.w);
        if (RELU) {
            v.x = fmaxf(v.x, 0.f); v.y = fmaxf(v.y, 0.f);
            v.z = fmaxf(v.z, 0.f); v.w = fmaxf(v.w, 0.f);
        }
        reinterpret_cast<float4*>(out)[(size_t)d * F4 + li] = v;
    }
}

// ---------------- launch ----------------
extern "C" void kernel_launch(void* const* d_in, const int* in_sizes, int n_in,
                              void* d_out, int out_size) {
    const float* X     = (const float*)d_in[0];
    const int*   EI    = (const int*)d_in[1];
    const float* W1    = (const float*)d_in[2];
    const float* asrc1 = (const float*)d_in[3];
    const float* adst1 = (const float*)d_in[4];
    const float* b1    = (const float*)d_in[5];
    const float* W2    = (const float*)d_in[6];
    const float* asrc2 = (const float*)d_in[7];
    const float* adst2 = (const float*)d_in[8];
    const float* b2    = (const float*)d_in[9];
    float* out = (float*)d_out;

    const int F_IN = 128;
    const int N = in_sizes[0] / F_IN;
    const int E = in_sizes[1] / 2;
    const int ET = E + N;
    const int* src = EI;
    const int* dst = EI + E;

    float *p_h, *p_x2;
    int *p_deg;
    cudaGetSymbolAddress((void**)&p_h, g_h);
    cudaGetSymbolAddress((void**)&p_x2, g_x2);
    cudaGetSymbolAddress((void**)&p_deg, g_deg);

    const int BT = 256;
    const int nb = (N + 1023) / 1024;
    const int edgeB = (ET + BT - 1) / BT;
    const int gB1 = (N + 127) / 128;

    // one-time side stream + events (resources persist; work per call is identical)
    static cudaStream_t s2 = nullptr;
    static cudaEvent_t evFork = nullptr, evJoin = nullptr;
    if (s2 == nullptr) {
        cudaStreamCreateWithFlags(&s2, cudaStreamNonBlocking);
        cudaEventCreateWithFlags(&evFork, cudaEventDisableTiming);
        cudaEventCreateWithFlags(&evJoin, cudaEventDisableTiming);
    }

    // ---- fork: CSR build on s2, GEMM1 on main stream ----
    cudaEventRecord(evFork, 0);
    cudaStreamWaitEvent(s2, evFork, 0);

    cudaMemsetAsync(p_deg, 0, (size_t)N * sizeof(int), s2);
    hist_kernel<<<edgeB, BT, 0, s2>>>(dst, E, ET);
    scan_partial_kernel<<<nb, 1024, 0, s2>>>(N);
    scan_final_kernel<<<nb, 1024, 0, s2>>>(N, nb);
    fill_kernel<<<edgeB, BT, 0, s2>>>(src, dst, E, ET);
    cudaEventRecord(evJoin, s2);

    // GEMM1 (+alpha1) on main stream, concurrent with CSR build
    gemm_alpha_kernel<128><<<gB1, BT>>>(X, W1, p_h, asrc1, adst1, N, F_IN);

    // ---- join ----
    cudaStreamWaitEvent(0, evJoin, 0);

    // gather layer 1 -> x2 (relu)
    gather_kernel<32, true><<<(N * 32 + BT - 1) / BT, BT>>>(p_h, b1, p_x2, N);

    // GEMM2 (+alpha2)
    gemm_alpha_kernel<64><<<gB1, BT>>>(p_x2, W2, p_h, asrc2, adst2, N, 128);

    // gather layer 2 -> out
    {
        long warps = (N + 1) / 2;
        gather_kernel<16, false><<<(unsigned)((warps * 32 + BT - 1) / BT), BT>>>(p_h, b2, out, N);
    }
}